// round 11
// baseline (speedup 1.0000x reference)
#include <cuda_runtime.h>
#include <cstdint>

#define NB_B 8192
#define LOD 60
#define LSD 120
#define AD 10
#define NB 15
#define HH 60
#define BX 64
#define BY 10
#define NT 640

typedef unsigned long long u64;

// ---- device scratch ----
__device__ float4 g_tmb[LOD * 7 * NB];     // (t11,t21,t12,t22) banded, k fastest

#define FMA2(acc, a, b) asm("fma.rn.f32x2 %0, %1, %2, %0;" : "+l"(acc) : "l"(a), "l"(b))
__device__ __forceinline__ float2 U2F(u64 v){ float2 r; asm("mov.b64 {%0,%1},%2;" : "=f"(r.x), "=f"(r.y) : "l"(v)); return r; }
__device__ __forceinline__ u64 F2U(float x, float y){ u64 r; asm("mov.b64 %0,{%1,%2};" : "=l"(r) : "f"(x), "f"(y)); return r; }
__device__ __forceinline__ u64 LDS64(uint32_t a){ u64 r; asm("ld.shared.b64 %0,[%1];" : "=l"(r) : "r"(a)); return r; }

// ======================= pack kernel (tiny, overlapped via PDL) =======================
__global__ void __launch_bounds__(512) pack_kernel(
    const float* __restrict__ tm11, const float* __restrict__ tm12,
    const float* __restrict__ tm21, const float* __restrict__ tm22)
{
    int idx = blockIdx.x * 512 + threadIdx.x;
    if (idx >= LOD * 7 * NB) return;
    int k = idx % NB;
    int jj = (idx / NB) % 7;
    int i = idx / (NB * 7);
    int j = i + jj - 3;
    float4 v = make_float4(0.f, 0.f, 0.f, 0.f);
    if (j >= 0 && j < LOD) {
        int off = k * LOD * LOD + i * LOD + j;
        v.x = tm11[off]; v.y = tm21[off];
        v.z = tm12[off]; v.w = tm22[off];
    }
    g_tmb[idx] = v;
}

// ======================= fused main kernel =======================
// persistent smem regions (float offsets)
#define SM_TMB   0        // 25200 floats; prep scratch first, then tmb (stage reuses tmb rows)
#define SM_Q     25200    // float4[60][65] (mu,ml,cu,cl) -> 15600
#define SM_CS2   40800    // [60][66] -> 3960
#define SM_COEF  44760    // u64[15][64] -> 1920
#define SM_TC    46680    // 120
#define SM_CTL   46800    // float2 pairs [120][33] -> 7920
#define SM_FLOATS 54720   // 218880 bytes

// prep scratch inside tmb region (dead before tmb load)
#define PW_WC   0         // packed float2[15][60] -> 1800
#define PW_W1   1800      // 600
#define PW_W2   2400      // duplicated float2[120][60] -> 14400
#define PW_B1   16800     // 60
#define PW_B2   16860     // 120
#define PW_BC   16980     // 15 (+pad)
#define PW_ACT  17000     // 10*66 = 660
#define PW_H    17660     // 60*66 = 3960
#define PW_LG   21620     // 15*66 = 990 -> 22610 < 25200

__device__ __forceinline__ void combine(
    u64 aXv, u64 aYv, bool diag, int jc, int x, const float* __restrict__ sm,
    float& nmu, float& nml, float& ncu, float& ncl, float& ncs)
{
    float2 X = U2F(aXv), Y = U2F(aYv);
    float t11 = X.x, t21 = X.y, t12 = Y.x, t22 = Y.y;
    if (diag) { t11 += 1.f; t22 += 1.f; }
    float4 q = ((const float4*)(sm + SM_Q))[jc * 65 + x];   // (mu, ml, cu, cl)
    float cs2 = sm[SM_CS2 + jc * 66 + x];
    nmu = fmaf(t11, q.x, fmaf(t12, q.y, nmu));
    nml = fmaf(t21, q.x, fmaf(t22, q.y, nml));
    ncu = fmaf(t11 * t11, q.z, fmaf(t11 * t12, cs2, fmaf(t12 * t12, q.w, ncu)));
    ncl = fmaf(t21 * t21, q.z, fmaf(t21 * t22, cs2, fmaf(t22 * t22, q.w, ncl)));
    ncs = fmaf(t21 * t11, q.z,
          fmaf(0.5f * fmaf(t22, t11, t21 * t12), cs2,
          fmaf(t22 * t12, q.w, ncs)));
}

// two-row mix: one coef load feeds 4*JN accumulator chains
template<int J0, int JN>
__device__ __forceinline__ void mix2(
    uint32_t row1, uint32_t row2, uint32_t coefA,
    u64* aX1, u64* aY1, u64* aX2, u64* aY2)
{
    #pragma unroll
    for (int jj = 0; jj < JN; jj++) { aX1[jj]=0; aY1[jj]=0; aX2[jj]=0; aY2[jj]=0; }
    #pragma unroll
    for (int k = 0; k < NB; k++) {
        u64 c2 = LDS64(coefA + (uint32_t)(k * 512));
        #pragma unroll
        for (int jj = 0; jj < JN; jj++) {
            u64 vX, vY, wX, wY;
            asm("ld.shared.v2.u64 {%0,%1},[%2];" : "=l"(vX), "=l"(vY)
                : "r"(row1 + (uint32_t)(((J0 + jj) * NB + k) * 16)));
            asm("ld.shared.v2.u64 {%0,%1},[%2];" : "=l"(wX), "=l"(wY)
                : "r"(row2 + (uint32_t)(((J0 + jj) * NB + k) * 16)));
            FMA2(aX1[jj], c2, vX); FMA2(aY1[jj], c2, vY);
            FMA2(aX2[jj], c2, wX); FMA2(aY2[jj], c2, wY);
        }
    }
}

__global__ void __launch_bounds__(NT, 1) acpredict_kernel(
    const float* __restrict__ post_mean, const float* __restrict__ cu_g,
    const float* __restrict__ cl_g, const float* __restrict__ cs_g,
    const float* __restrict__ action, const float* __restrict__ log_noise,
    const float* __restrict__ w_coef, const float* __restrict__ b_coef,
    const float* __restrict__ w_c1, const float* __restrict__ b_c1,
    const float* __restrict__ w_c2, const float* __restrict__ b_c2,
    float* __restrict__ out)
{
    extern __shared__ float sm[];
    const int x   = threadIdx.x;           // 0..63 : batch element
    const int y   = threadIdx.y;           // 0..9  : row group (pair of warps)
    const int tid = y * BX + x;
    const int b0  = blockIdx.x * BX;

    // ---- phase 0: load inputs + prep weights (tmb region holds scratch) ----
    for (int e = tid; e < BX * LSD; e += NT) {
        int bl = e / LSD, d = e % LSD;
        float v = post_mean[(b0 + bl) * LSD + d];
        int j = (d < LOD) ? d : d - LOD;
        sm[SM_Q + (j * 65 + bl) * 4 + (d < LOD ? 0 : 1)] = v;
    }
    for (int e = tid; e < BX * LOD; e += NT) {
        int bl = e / LOD, j = e % LOD;
        sm[SM_Q + (j * 65 + bl) * 4 + 2] = cu_g[(b0 + bl) * LOD + j];
        sm[SM_Q + (j * 65 + bl) * 4 + 3] = cl_g[(b0 + bl) * LOD + j];
        sm[SM_CS2 + j * 66 + bl] = 2.f * cs_g[(b0 + bl) * LOD + j];
    }
    for (int e = tid; e < BX * AD; e += NT) {
        int bl = e / AD, d = e % AD;
        sm[PW_ACT + d * 66 + bl] = action[(b0 + bl) * AD + d];
    }
    // w_coef packed as (w[k][j], w[k][j+60]) pairs
    for (int e = tid; e < NB * LSD; e += NT) {
        int k = e / LSD, d = e % LSD;
        int j = (d < LOD) ? d : d - LOD;
        sm[PW_WC + (k * LOD + j) * 2 + (d < LOD ? 0 : 1)] = w_coef[e];
    }
    for (int e = tid; e < HH * AD; e += NT)  sm[PW_W1 + e] = w_c1[e];
    // w_c2 duplicated as (w,w) pairs
    for (int e = tid; e < LSD * HH; e += NT) {
        float v = w_c2[e];
        ((u64*)(sm + PW_W2))[e] = F2U(v, v);
    }
    if (tid < HH)  sm[PW_B1 + tid] = b_c1[tid];
    if (tid < LSD) sm[PW_B2 + tid] = b_c2[tid];
    if (tid < NB)  sm[PW_BC + tid] = b_coef[tid];
    if (tid < LSD) {
        float v = log_noise[tid];
        sm[SM_TC + tid] = (v < 0.f) ? __expf(v) : v + 1.f;
    }
    __syncthreads();

    // ---- phase 1: logits (packed f32x2) + hidden layer ----
    for (int e = tid; e < NB * BX; e += NT) {
        int k = e / BX, bl = e % BX;
        u64 acc = 0;
        const u64* wcP = (const u64*)(sm + PW_WC) + k * LOD;     // warp-uniform
        const u64* mmP = (const u64*)(sm + SM_Q);                // (mu,ml) = 1st half of quad
        #pragma unroll 4
        for (int j = 0; j < LOD; j++)
            FMA2(acc, wcP[j], mmP[(j * 65 + bl) * 2]);
        float2 p = U2F(acc);
        sm[PW_LG + k * 66 + bl] = p.x + p.y + sm[PW_BC + k];
    }
    for (int e = tid; e < HH * BX; e += NT) {
        int i = e / BX, bl = e % BX;
        float hv = sm[PW_B1 + i];
        #pragma unroll
        for (int d = 0; d < AD; d++)
            hv = fmaf(sm[PW_W1 + i * AD + d], sm[PW_ACT + d * 66 + bl], hv);
        sm[PW_H + i * 66 + bl] = fmaxf(hv, 0.f);
    }
    __syncthreads();

    // ---- phase 2: softmax (-> SM_COEF) + control MLP (channel-tiled x4) ----
    if (tid < BX) {
        const int bl = tid;
        float mx = -1e30f;
        #pragma unroll
        for (int k = 0; k < NB; k++) mx = fmaxf(mx, sm[PW_LG + k * 66 + bl]);
        float ex[NB], sum = 0.f;
        #pragma unroll
        for (int k = 0; k < NB; k++) {
            ex[k] = __expf(sm[PW_LG + k * 66 + bl] - mx);
            sum += ex[k];
        }
        float inv = 1.f / sum;
        #pragma unroll
        for (int k = 0; k < NB; k++) {
            float c = ex[k] * inv;
            ((u64*)(sm + SM_COEF))[k * BX + bl] = F2U(c, c);
        }
    }
    for (int e = tid; e < 30 * (BX / 2); e += NT) {
        int g = e / (BX / 2), blp = e % (BX / 2);
        int c0 = g * 4;
        u64 acc[4];
        #pragma unroll
        for (int q = 0; q < 4; q++) {
            float bb = sm[PW_B2 + c0 + q];
            acc[q] = F2U(bb, bb);
        }
        const u64* w2P = (const u64*)(sm + PW_W2);
        const u64* hP  = (const u64*)(sm + PW_H);
        #pragma unroll 4
        for (int m = 0; m < HH; m++) {
            u64 hm = hP[m * 33 + blp];
            #pragma unroll
            for (int q = 0; q < 4; q++)
                FMA2(acc[q], w2P[(c0 + q) * HH + m], hm);
        }
        #pragma unroll
        for (int q = 0; q < 4; q++)
            ((u64*)(sm + SM_CTL))[(c0 + q) * 33 + blp] = acc[q];
    }
    __syncthreads();

    // ---- phase 3: wait for pack kernel, load tmb into smem ----
    cudaGridDependencySynchronize();
    {
        float4* t4 = (float4*)sm;
        for (int e = tid; e < LOD * 7 * NB; e += NT) t4[e] = g_tmb[e];
    }
    __syncthreads();

    // ---- phase 4: two-row mix + combine; stage into own dead tmb slots ----
    const uint32_t sbase = (uint32_t)__cvta_generic_to_shared(sm);
    const uint32_t coefA = sbase + SM_COEF * 4 + (uint32_t)x * 8u;

    #pragma unroll
    for (int t = 0; t < 3; t++) {
        const int i1 = y + 10 * t;          // 0..29
        const int i2 = i1 + 30;             // 30..59
        const uint32_t row1 = sbase + (uint32_t)(i1 * 7 * NB * 16);
        const uint32_t row2 = sbase + (uint32_t)(i2 * 7 * NB * 16);

        float nmu1=0.f, nml1=0.f, ncu1=0.f, ncl1=0.f, ncs1=0.f;
        float nmu2=0.f, nml2=0.f, ncu2=0.f, ncl2=0.f, ncs2=0.f;

        {   // pass A: jj 0..3
            u64 aX1[4], aY1[4], aX2[4], aY2[4];
            mix2<0, 4>(row1, row2, coefA, aX1, aY1, aX2, aY2);
            #pragma unroll
            for (int jj = 0; jj < 4; jj++) {
                int jc1 = max(i1 + jj - 3, 0);
                combine(aX1[jj], aY1[jj], jj == 3, jc1, x, sm, nmu1, nml1, ncu1, ncl1, ncs1);
                int jc2 = i2 + jj - 3;      // 27..59, in range
                combine(aX2[jj], aY2[jj], jj == 3, jc2, x, sm, nmu2, nml2, ncu2, ncl2, ncs2);
            }
        }
        {   // pass B: jj 4..6
            u64 aX1[3], aY1[3], aX2[3], aY2[3];
            mix2<4, 3>(row1, row2, coefA, aX1, aY1, aX2, aY2);
            #pragma unroll
            for (int q = 0; q < 3; q++) {
                int jc1 = i1 + 1 + q;       // 1..32, in range
                combine(aX1[q], aY1[q], false, jc1, x, sm, nmu1, nml1, ncu1, ncl1, ncs1);
                int jc2 = min(i2 + 1 + q, LOD - 1);
                combine(aX2[q], aY2[q], false, jc2, x, sm, nmu2, nml2, ncu2, ncl2, ncs2);
            }
        }

        // pair barrier: both warps of this y done READING tmb rows i1, i2
        asm volatile("bar.sync %0, 64;" :: "r"(y + 1) : "memory");

        float* s1 = sm + i1 * 420;          // rows' own dead tmb slots
        s1[0*64 + x] = nmu1; s1[1*64 + x] = nml1; s1[2*64 + x] = ncu1;
        s1[3*64 + x] = ncl1; s1[4*64 + x] = ncs1;
        float* s2 = sm + i2 * 420;
        s2[0*64 + x] = nmu2; s2[1*64 + x] = nml2; s2[2*64 + x] = ncu2;
        s2[3*64 + x] = ncl2; s2[4*64 + x] = ncs2;
    }
    __syncthreads();

    // ---- phase 5: coalesced stores; fold in control + trans_cov ----
    for (int e = tid; e < BX * 300; e += NT) {
        int bl = e / 300, c = e % 300;
        int q = c / 60, i = c % 60;
        float v = sm[i * 420 + q * 64 + bl];
        int bb = b0 + bl;
        if (c < 120) {
            v += sm[SM_CTL + c * 66 + bl];
            out[bb * 120 + c] = v;
        } else {
            if (c < 240) v += sm[SM_TC + (c - 120)];
            out[NB_B * 60 * q + bb * 60 + i] = v;
        }
    }
}

extern "C" void kernel_launch(void* const* d_in, const int* in_sizes, int n_in,
                              void* d_out, int out_size) {
    const float* post_mean = (const float*)d_in[0];
    const float* cu        = (const float*)d_in[1];
    const float* cl        = (const float*)d_in[2];
    const float* cs        = (const float*)d_in[3];
    const float* action    = (const float*)d_in[4];
    const float* tm11      = (const float*)d_in[5];
    const float* tm12      = (const float*)d_in[6];
    const float* tm21      = (const float*)d_in[7];
    const float* tm22      = (const float*)d_in[8];
    const float* log_noise = (const float*)d_in[9];
    const float* w_coef    = (const float*)d_in[10];
    const float* b_coef    = (const float*)d_in[11];
    const float* w_c1      = (const float*)d_in[12];
    const float* b_c1      = (const float*)d_in[13];
    const float* w_c2      = (const float*)d_in[14];
    const float* b_c2      = (const float*)d_in[15];
    float* out = (float*)d_out;

    static bool attr_done = false;
    if (!attr_done) {
        cudaFuncSetAttribute(acpredict_kernel,
            cudaFuncAttributeMaxDynamicSharedMemorySize, SM_FLOATS * 4);
        attr_done = true;
    }

    // primary: tiny tmb pack
    pack_kernel<<<13, 512>>>(tm11, tm12, tm21, tm22);

    // secondary: fused main kernel with PDL (preamble overlaps pack)
    cudaLaunchConfig_t cfg = {};
    cfg.gridDim = dim3(NB_B / BX);
    cfg.blockDim = dim3(BX, BY);
    cfg.dynamicSmemBytes = SM_FLOATS * 4;
    cfg.stream = 0;
    cudaLaunchAttribute at[1];
    at[0].id = cudaLaunchAttributeProgrammaticStreamSerialization;
    at[0].val.programmaticStreamSerializationAllowed = 1;
    cfg.attrs = at;
    cfg.numAttrs = 1;
    cudaLaunchKernelEx(&cfg, acpredict_kernel,
                       post_mean, cu, cl, cs, action, log_noise,
                       w_coef, b_coef, w_c1, b_c1, w_c2, b_c2, out);
}

// round 12
// speedup vs baseline: 1.0442x; 1.0442x over previous
#include <cuda_runtime.h>
#include <cstdint>

#define NB_B 8192
#define LOD 60
#define LSD 120
#define AD 10
#define NB 15
#define HH 60
#define BT 64      // batch tile per CTA
#define XT 32      // threads in x (lane owns batch x and x+32)
#define BY 20
#define NT 640

typedef unsigned long long u64;

// ---- device scratch ----
__device__ float4 g_tmb[LOD * 7 * NB];     // (t11,t21,t12,t22) banded, k fastest

#define FMA2(acc, a, b) asm("fma.rn.f32x2 %0, %1, %2, %0;" : "+l"(acc) : "l"(a), "l"(b))
__device__ __forceinline__ float2 U2F(u64 v){ float2 r; asm("mov.b64 {%0,%1},%2;" : "=f"(r.x), "=f"(r.y) : "l"(v)); return r; }
__device__ __forceinline__ u64 F2U(float x, float y){ u64 r; asm("mov.b64 %0,{%1,%2};" : "=l"(r) : "f"(x), "f"(y)); return r; }
__device__ __forceinline__ u64 LDS64(uint32_t a){ u64 r; asm("ld.shared.b64 %0,[%1];" : "=l"(r) : "r"(a)); return r; }

// ======================= pack kernel (tiny, overlapped via PDL) =======================
__global__ void __launch_bounds__(512) pack_kernel(
    const float* __restrict__ tm11, const float* __restrict__ tm12,
    const float* __restrict__ tm21, const float* __restrict__ tm22)
{
    int idx = blockIdx.x * 512 + threadIdx.x;
    if (idx >= LOD * 7 * NB) return;
    int k = idx % NB;
    int jj = (idx / NB) % 7;
    int i = idx / (NB * 7);
    int j = i + jj - 3;
    float4 v = make_float4(0.f, 0.f, 0.f, 0.f);
    if (j >= 0 && j < LOD) {
        int off = k * LOD * LOD + i * LOD + j;
        v.x = tm11[off]; v.y = tm21[off];
        v.z = tm12[off]; v.w = tm22[off];
    }
    g_tmb[idx] = v;
}

// ======================= fused main kernel =======================
// persistent smem regions (float offsets)
#define SM_TMB   0        // 25200 floats; prep scratch first, then tmb (stage reuses tmb rows)
#define SM_MUML  25200    // float2[60][66] -> 7920
#define SM_CUCL  33120    // 7920
#define SM_CS2   41040    // 3960
#define SM_COEF  45000    // u64[15][64] -> 1920
#define SM_TC    46920    // 120
#define SM_CTL   47040    // float2 pairs [120][33] -> 7920
#define SM_FLOATS 54960   // 219840 bytes

// prep scratch inside tmb region (dead before tmb load)
#define PW_WC   0         // packed float2[15][60] -> 1800
#define PW_W1   1800      // 600
#define PW_W2   2400      // duplicated float2[120][60] -> 14400
#define PW_B1   16800     // 60
#define PW_B2   16860     // 120
#define PW_BC   16980     // 15 (+pad)
#define PW_ACT  17000     // 10*66 = 660
#define PW_H    17660     // 60*66 = 3960
#define PW_LG   21620     // 15*66 = 990 -> 22610 < 25200

__device__ __forceinline__ void combine(
    u64 aXv, u64 aYv, bool diag, int jc, int bl, const float* __restrict__ sm,
    float& nmu, float& nml, float& ncu, float& ncl, float& ncs)
{
    float2 X = U2F(aXv), Y = U2F(aYv);
    float t11 = X.x, t21 = X.y, t12 = Y.x, t22 = Y.y;
    if (diag) { t11 += 1.f; t22 += 1.f; }
    float2 mm = ((const float2*)(sm + SM_MUML))[jc * 66 + bl];   // (mu, ml)
    float2 cc = ((const float2*)(sm + SM_CUCL))[jc * 66 + bl];   // (cu, cl)
    float cs2 = sm[SM_CS2 + jc * 66 + bl];
    nmu = fmaf(t11, mm.x, fmaf(t12, mm.y, nmu));
    nml = fmaf(t21, mm.x, fmaf(t22, mm.y, nml));
    ncu = fmaf(t11 * t11, cc.x, fmaf(t11 * t12, cs2, fmaf(t12 * t12, cc.y, ncu)));
    ncl = fmaf(t21 * t21, cc.x, fmaf(t21 * t22, cs2, fmaf(t22 * t22, cc.y, ncl)));
    ncs = fmaf(t21 * t11, cc.x,
          fmaf(0.5f * fmaf(t22, t11, t21 * t12), cs2,
          fmaf(t22 * t12, cc.y, ncs)));
}

// one k-walk over JN diagonals: ONE tmb load feeds both batch halves (4 chains)
template<int J0, int JN>
__device__ __forceinline__ void mix_halves(
    uint32_t tmbRow, uint32_t coefA,
    u64* aXA, u64* aYA, u64* aXB, u64* aYB)
{
    #pragma unroll
    for (int jj = 0; jj < JN; jj++) { aXA[jj]=0; aYA[jj]=0; aXB[jj]=0; aYB[jj]=0; }
    #pragma unroll
    for (int k = 0; k < NB; k++) {
        u64 cA = LDS64(coefA + (uint32_t)(k * 512));          // batch x
        u64 cB = LDS64(coefA + (uint32_t)(k * 512 + 256));    // batch x+32
        #pragma unroll
        for (int jj = 0; jj < JN; jj++) {
            u64 vX, vY;   // (t11,t21), (t12,t22) — warp-uniform broadcast, loaded ONCE
            asm("ld.shared.v2.u64 {%0,%1},[%2];"
                : "=l"(vX), "=l"(vY)
                : "r"(tmbRow + (uint32_t)(((J0 + jj) * NB + k) * 16)));
            FMA2(aXA[jj], cA, vX); FMA2(aYA[jj], cA, vY);
            FMA2(aXB[jj], cB, vX); FMA2(aYB[jj], cB, vY);
        }
    }
}

__global__ void __launch_bounds__(NT, 1) acpredict_kernel(
    const float* __restrict__ post_mean, const float* __restrict__ cu_g,
    const float* __restrict__ cl_g, const float* __restrict__ cs_g,
    const float* __restrict__ action, const float* __restrict__ log_noise,
    const float* __restrict__ w_coef, const float* __restrict__ b_coef,
    const float* __restrict__ w_c1, const float* __restrict__ b_c1,
    const float* __restrict__ w_c2, const float* __restrict__ b_c2,
    float* __restrict__ out)
{
    extern __shared__ float sm[];
    const int x   = threadIdx.x;           // 0..31 : batch elements x and x+32
    const int y   = threadIdx.y;           // 0..19 : row group (ONE warp)
    const int tid = y * XT + x;
    const int b0  = blockIdx.x * BT;

    // ---- phase 0: load inputs + prep weights (tmb region holds scratch) ----
    for (int e = tid; e < BT * LSD; e += NT) {
        int bl = e / LSD, d = e % LSD;
        float v = post_mean[(b0 + bl) * LSD + d];
        int j = (d < LOD) ? d : d - LOD;
        sm[SM_MUML + (j * 66 + bl) * 2 + (d < LOD ? 0 : 1)] = v;
    }
    for (int e = tid; e < BT * LOD; e += NT) {
        int bl = e / LOD, j = e % LOD;
        sm[SM_CUCL + (j * 66 + bl) * 2 + 0] = cu_g[(b0 + bl) * LOD + j];
        sm[SM_CUCL + (j * 66 + bl) * 2 + 1] = cl_g[(b0 + bl) * LOD + j];
        sm[SM_CS2 + j * 66 + bl] = 2.f * cs_g[(b0 + bl) * LOD + j];
    }
    for (int e = tid; e < BT * AD; e += NT) {
        int bl = e / AD, d = e % AD;
        sm[PW_ACT + d * 66 + bl] = action[(b0 + bl) * AD + d];
    }
    // w_coef packed as (w[k][j], w[k][j+60]) pairs
    for (int e = tid; e < NB * LSD; e += NT) {
        int k = e / LSD, d = e % LSD;
        int j = (d < LOD) ? d : d - LOD;
        sm[PW_WC + (k * LOD + j) * 2 + (d < LOD ? 0 : 1)] = w_coef[e];
    }
    for (int e = tid; e < HH * AD; e += NT)  sm[PW_W1 + e] = w_c1[e];
    // w_c2 duplicated as (w,w) pairs
    for (int e = tid; e < LSD * HH; e += NT) {
        float v = w_c2[e];
        ((u64*)(sm + PW_W2))[e] = F2U(v, v);
    }
    if (tid < HH)  sm[PW_B1 + tid] = b_c1[tid];
    if (tid < LSD) sm[PW_B2 + tid] = b_c2[tid];
    if (tid < NB)  sm[PW_BC + tid] = b_coef[tid];
    if (tid < LSD) {
        float v = log_noise[tid];
        sm[SM_TC + tid] = (v < 0.f) ? __expf(v) : v + 1.f;
    }
    __syncthreads();

    // ---- phase 1: logits (packed f32x2) + hidden layer ----
    for (int e = tid; e < NB * BT; e += NT) {
        int k = e / BT, bl = e % BT;
        u64 acc = 0;
        const u64* wcP = (const u64*)(sm + PW_WC) + k * LOD;     // warp-uniform
        const u64* mmP = (const u64*)(sm + SM_MUML);
        #pragma unroll 4
        for (int j = 0; j < LOD; j++)
            FMA2(acc, wcP[j], mmP[j * 66 + bl]);
        float2 p = U2F(acc);
        sm[PW_LG + k * 66 + bl] = p.x + p.y + sm[PW_BC + k];
    }
    for (int e = tid; e < HH * BT; e += NT) {
        int i = e / BT, bl = e % BT;
        float hv = sm[PW_B1 + i];
        #pragma unroll
        for (int d = 0; d < AD; d++)
            hv = fmaf(sm[PW_W1 + i * AD + d], sm[PW_ACT + d * 66 + bl], hv);
        sm[PW_H + i * 66 + bl] = fmaxf(hv, 0.f);
    }
    __syncthreads();

    // ---- phase 2: softmax (-> SM_COEF) + control MLP (channel-tiled x4) ----
    if (tid < BT) {
        const int bl = tid;
        float mx = -1e30f;
        #pragma unroll
        for (int k = 0; k < NB; k++) mx = fmaxf(mx, sm[PW_LG + k * 66 + bl]);
        float ex[NB], sum = 0.f;
        #pragma unroll
        for (int k = 0; k < NB; k++) {
            ex[k] = __expf(sm[PW_LG + k * 66 + bl] - mx);
            sum += ex[k];
        }
        float inv = 1.f / sum;
        #pragma unroll
        for (int k = 0; k < NB; k++) {
            float c = ex[k] * inv;
            ((u64*)(sm + SM_COEF))[k * BT + bl] = F2U(c, c);
        }
    }
    for (int e = tid; e < 30 * (BT / 2); e += NT) {
        int g = e / (BT / 2), blp = e % (BT / 2);
        int c0 = g * 4;
        u64 acc[4];
        #pragma unroll
        for (int q = 0; q < 4; q++) {
            float bb = sm[PW_B2 + c0 + q];
            acc[q] = F2U(bb, bb);
        }
        const u64* w2P = (const u64*)(sm + PW_W2);
        const u64* hP  = (const u64*)(sm + PW_H);
        #pragma unroll 4
        for (int m = 0; m < HH; m++) {
            u64 hm = hP[m * 33 + blp];
            #pragma unroll
            for (int q = 0; q < 4; q++)
                FMA2(acc[q], w2P[(c0 + q) * HH + m], hm);
        }
        #pragma unroll
        for (int q = 0; q < 4; q++)
            ((u64*)(sm + SM_CTL))[(c0 + q) * 33 + blp] = acc[q];
    }
    __syncthreads();

    // ---- phase 3: wait for pack kernel, load tmb into smem ----
    cudaGridDependencySynchronize();
    {
        float4* t4 = (float4*)sm;
        for (int e = tid; e < LOD * 7 * NB; e += NT) t4[e] = g_tmb[e];
    }
    __syncthreads();

    // ---- phase 4: one warp per row, two batch halves per lane ----
    const uint32_t sbase = (uint32_t)__cvta_generic_to_shared(sm);
    const uint32_t coefA = sbase + SM_COEF * 4 + (uint32_t)x * 8u;

    #pragma unroll
    for (int t = 0; t < 3; t++) {
        const int i = y + BY * t;          // 0..59, each row owned by ONE warp
        const uint32_t tmbRow = sbase + (uint32_t)(i * 7 * NB * 16);

        float nmu1=0.f, nml1=0.f, ncu1=0.f, ncl1=0.f, ncs1=0.f;
        float nmu2=0.f, nml2=0.f, ncu2=0.f, ncl2=0.f, ncs2=0.f;

        {   // pass A: jj 0..3
            u64 aXA[4], aYA[4], aXB[4], aYB[4];
            mix_halves<0, 4>(tmbRow, coefA, aXA, aYA, aXB, aYB);
            #pragma unroll
            for (int jj = 0; jj < 4; jj++) {
                int jc = max(i + jj - 3, 0);
                combine(aXA[jj], aYA[jj], jj == 3, jc, x,      sm, nmu1, nml1, ncu1, ncl1, ncs1);
                combine(aXB[jj], aYB[jj], jj == 3, jc, x + 32, sm, nmu2, nml2, ncu2, ncl2, ncs2);
            }
        }
        {   // pass B: jj 4..6
            u64 aXA[3], aYA[3], aXB[3], aYB[3];
            mix_halves<4, 3>(tmbRow, coefA, aXA, aYA, aXB, aYB);
            #pragma unroll
            for (int q = 0; q < 3; q++) {
                int jc = min(i + 1 + q, LOD - 1);
                combine(aXA[q], aYA[q], false, jc, x,      sm, nmu1, nml1, ncu1, ncl1, ncs1);
                combine(aXB[q], aYB[q], false, jc, x + 32, sm, nmu2, nml2, ncu2, ncl2, ncs2);
            }
        }

        // stage into this row's own dead tmb slot — row i is owned solely by
        // this warp, so no cross-warp sync is needed before overwriting it.
        float* stg = sm + i * 420;
        stg[0*64 + x] = nmu1;  stg[0*64 + x + 32] = nmu2;
        stg[1*64 + x] = nml1;  stg[1*64 + x + 32] = nml2;
        stg[2*64 + x] = ncu1;  stg[2*64 + x + 32] = ncu2;
        stg[3*64 + x] = ncl1;  stg[3*64 + x + 32] = ncl2;
        stg[4*64 + x] = ncs1;  stg[4*64 + x + 32] = ncs2;
    }
    __syncthreads();

    // ---- phase 5: coalesced stores; fold in control + trans_cov ----
    for (int e = tid; e < BT * 300; e += NT) {
        int bl = e / 300, c = e % 300;
        int q = c / 60, i = c % 60;
        float v = sm[i * 420 + q * 64 + bl];
        int bb = b0 + bl;
        if (c < 120) {
            v += sm[SM_CTL + c * 66 + bl];
            out[bb * 120 + c] = v;
        } else {
            if (c < 240) v += sm[SM_TC + (c - 120)];
            out[NB_B * 60 * q + bb * 60 + i] = v;
        }
    }
}

extern "C" void kernel_launch(void* const* d_in, const int* in_sizes, int n_in,
                              void* d_out, int out_size) {
    const float* post_mean = (const float*)d_in[0];
    const float* cu        = (const float*)d_in[1];
    const float* cl        = (const float*)d_in[2];
    const float* cs        = (const float*)d_in[3];
    const float* action    = (const float*)d_in[4];
    const float* tm11      = (const float*)d_in[5];
    const float* tm12      = (const float*)d_in[6];
    const float* tm21      = (const float*)d_in[7];
    const float* tm22      = (const float*)d_in[8];
    const float* log_noise = (const float*)d_in[9];
    const float* w_coef    = (const float*)d_in[10];
    const float* b_coef    = (const float*)d_in[11];
    const float* w_c1      = (const float*)d_in[12];
    const float* b_c1      = (const float*)d_in[13];
    const float* w_c2      = (const float*)d_in[14];
    const float* b_c2      = (const float*)d_in[15];
    float* out = (float*)d_out;

    static bool attr_done = false;
    if (!attr_done) {
        cudaFuncSetAttribute(acpredict_kernel,
            cudaFuncAttributeMaxDynamicSharedMemorySize, SM_FLOATS * 4);
        attr_done = true;
    }

    // primary: tiny tmb pack
    pack_kernel<<<13, 512>>>(tm11, tm12, tm21, tm22);

    // secondary: fused main kernel with PDL (preamble overlaps pack)
    cudaLaunchConfig_t cfg = {};
    cfg.gridDim = dim3(NB_B / BT);
    cfg.blockDim = dim3(XT, BY);
    cfg.dynamicSmemBytes = SM_FLOATS * 4;
    cfg.stream = 0;
    cudaLaunchAttribute at[1];
    at[0].id = cudaLaunchAttributeProgrammaticStreamSerialization;
    at[0].val.programmaticStreamSerializationAllowed = 1;
    cfg.attrs = at;
    cfg.numAttrs = 1;
    cudaLaunchKernelEx(&cfg, acpredict_kernel,
                       post_mean, cu, cl, cs, action, log_noise,
                       w_coef, b_coef, w_c1, b_c1, w_c2, b_c2, out);
}